// round 14
// baseline (speedup 1.0000x reference)
#include <cuda_runtime.h>
#include <cuda_fp16.h>
#include <cstdint>

#define BB   32
#define DIM  512
#define HWN  4096
#define KC   64
#define DQ   3
#define MM   192
#define NTILE 128           // hw per CTA
#define NT   32             // 4096/128
#define KSTAGE 32
#define NSTAGE 16           // 512/32
#define NTHREADS 512

// dynamic smem layout (mainloop)
#define W_BUF_B   15360     // per buffer: hi only (192*80)
#define OFF_W     0
#define OFF_BH    30720     // fp16 feat [k32][n128] swizzled, 2 x 8192
// epilogue staging reuses dyn as [192][272B]: 52224 B
#define KV_PITCH  272
#define SMEM_TOT  52224

// ---------------- scratch ----------------
__device__ __half   g_kv[(size_t)BB * MM * HWN];     // [b][m][hw]  (fp16)
__device__ float    g_part[BB * NT * KC];
__device__ float    g_loss[BB * DQ * 4];
__device__ unsigned g_Whi[MM * DIM / 2];             // f16x2, [m][kpair]
__device__ unsigned g_cnt;                           // completion counter (self-resetting)

// ---------------- helpers ----------------
__device__ __forceinline__ uint32_t smem_u32(const void* p) {
    uint32_t a;
    asm("{ .reg .u64 t; cvta.to.shared.u64 t, %1; cvt.u32.u64 %0, t; }" : "=r"(a) : "l"(p));
    return a;
}
__device__ __forceinline__ void cp16(uint32_t smem, const void* gmem) {
    unsigned long long ga = (unsigned long long)__cvta_generic_to_global(gmem);
    asm volatile("cp.async.cg.shared.global [%0], [%1], 16;" :: "r"(smem), "l"(ga));
}
__device__ __forceinline__ void cp_commit() { asm volatile("cp.async.commit_group;"); }
__device__ __forceinline__ void cp_wait0() { asm volatile("cp.async.wait_group 0;" ::: "memory"); }

__device__ __forceinline__ void ldm4(unsigned* r, uint32_t a) {
    asm volatile("ldmatrix.sync.aligned.m8n8.x4.shared.b16 {%0,%1,%2,%3}, [%4];"
                 : "=r"(r[0]), "=r"(r[1]), "=r"(r[2]), "=r"(r[3]) : "r"(a));
}
__device__ __forceinline__ void ldm4t(unsigned* r, uint32_t a) {
    asm volatile("ldmatrix.sync.aligned.m8n8.x4.trans.shared.b16 {%0,%1,%2,%3}, [%4];"
                 : "=r"(r[0]), "=r"(r[1]), "=r"(r[2]), "=r"(r[3]) : "r"(a));
}
__device__ __forceinline__ void mma16816(float* c, const unsigned* a, const unsigned* b) {
    asm volatile("mma.sync.aligned.m16n8k16.row.col.f32.f16.f16.f32 "
                 "{%0,%1,%2,%3}, {%4,%5,%6,%7}, {%8,%9}, {%0,%1,%2,%3};"
                 : "+f"(c[0]), "+f"(c[1]), "+f"(c[2]), "+f"(c[3])
                 : "r"(a[0]), "r"(a[1]), "r"(a[2]), "r"(a[3]), "r"(b[0]), "r"(b[1]));
}
// pack fp16x2: {lo half = x0, hi half = x1}
__device__ __forceinline__ unsigned cvt2(float x0, float x1) {
    unsigned r;
    asm("cvt.rn.f16x2.f32 %0, %1, %2;" : "=r"(r) : "f"(x1), "f"(x0));
    return r;
}

// ============================================================================
// Pass 0: W fp32 -> fp16 packed k-pairs
// ============================================================================
__global__ void wsplit_kernel(const float* __restrict__ W) {
    int i = blockIdx.x * 256 + threadIdx.x;
    if (i >= MM * DIM / 2) return;
    g_Whi[i] = cvt2(W[2 * i], W[2 * i + 1]);
}

// ============================================================================
// Pass 1: C[m,hw] = W @ feat per batch via single-pass fp16 mma.sync.
// 512 threads, 16 warps = 4m x 4n (warp tile m48 x n32) — 4 warps per SMSP
// keep the tensor pipe fed through ldmatrix/barrier windows.
// Feat: direct LDG -> cvt -> STS (serial at stage top, R12 order).
// Epilogue: smem-staged coalesced kv store.
// ============================================================================
__global__ __launch_bounds__(NTHREADS)
void kv_mma_kernel(const float* __restrict__ feat,
                   const float* __restrict__ query) {
    extern __shared__ __align__(16) unsigned char dyn[];
    __shared__ float sdist[MM][4];

    const int tid  = threadIdx.x;
    const int b    = blockIdx.y;
    const int hw0  = blockIdx.x * NTILE;
    const int lane = tid & 31, wid = tid >> 5;
    const int warp_m = wid >> 2;          // 0..3 -> m offset *48
    const int warp_n = wid & 3;           // 0..3 -> hw offset *32
    const int g  = lane >> 2, tg = lane & 3;

    const uint32_t sbase = smem_u32(dyn);

    // feat conversion addressing: thread covers k=ck, n=[cn, cn+8)
    const int ck = tid >> 4;              // 0..31
    const int cn = (tid & 15) * 8;        // 0..120
    const uint32_t sts0 = (uint32_t)(ck * 256 + (((cn * 2)) ^ ((ck & 7) << 4)));

    auto issueW = [&](int s, int buf) {
        const uint32_t wb = sbase + OFF_W + (uint32_t)buf * W_BUF_B;
        #pragma unroll
        for (int j = 0; j < 2; j++) {                // W hi: 192 rows x 4 chunks = 768
            int i = tid + j * NTHREADS;
            if (i < 768) {
                int m = i >> 2, c = i & 3;
                cp16(wb + m * 80 + c * 16, g_Whi + m * 256 + s * 16 + c * 4);
            }
        }
    };

    float acc[3][4][4];
    #pragma unroll
    for (int mi = 0; mi < 3; mi++)
        #pragma unroll
        for (int ni = 0; ni < 4; ni++)
            #pragma unroll
            for (int r = 0; r < 4; r++) acc[mi][ni][r] = 0.f;

    // B ldmatrix lane addressing
    const int b_r      = lane & 7;
    const int b_khalf  = (lane >> 3) & 1;
    const int b_nhalf  = (lane >> 4) & 1;
    const uint32_t b_sw = (uint32_t)(b_r << 4);
    const uint32_t b_n0 = (uint32_t)(warp_n * 32 + b_nhalf * 8);

    // prefetch feat stage 0
    float4 f0, f1;
    {
        const float* fp = feat + ((size_t)(b * DIM + ck)) * HWN + hw0 + cn;
        f0 = *(const float4*)(fp);
        f1 = *(const float4*)(fp + 4);
    }
    issueW(0, 0); cp_commit();

    for (int s = 0; s < NSTAGE; s++) {
        const int buf = s & 1;
        const uint32_t bhb = sbase + OFF_BH + (uint32_t)buf * 8192;

        // ---- convert this stage's feat regs -> fp16 smem (one STS.128) ----
        {
            unsigned h0 = cvt2(f0.x, f0.y), h1 = cvt2(f0.z, f0.w);
            unsigned h2 = cvt2(f1.x, f1.y), h3 = cvt2(f1.z, f1.w);
            *(uint4*)(dyn + OFF_BH + buf * 8192 + sts0) = make_uint4(h0, h1, h2, h3);
        }
        // ---- prefetch feat for next stage ----
        if (s + 1 < NSTAGE) {
            const float* fp = feat + ((size_t)(b * DIM + (s + 1) * KSTAGE + ck)) * HWN + hw0 + cn;
            f0 = *(const float4*)(fp);
            f1 = *(const float4*)(fp + 4);
        }
        cp_wait0();          // W for stage s landed
        __syncthreads();     // the only barrier per stage
        if (s + 1 < NSTAGE) { issueW(s + 1, buf ^ 1); cp_commit(); }

        const uint32_t wbh = sbase + OFF_W + (uint32_t)buf * W_BUF_B;

        #pragma unroll
        for (int ks = 0; ks < 2; ks++) {
            // ---- B fragments via ldmatrix.trans: 2 halves of n32 ----
            unsigned bh[2][4];
            {
                uint32_t k = (uint32_t)(ks * 16 + b_khalf * 8 + b_r);
                uint32_t rowb = bhb + k * 256;
                #pragma unroll
                for (int q = 0; q < 2; q++) {
                    uint32_t coff = (((b_n0 + q * 16) * 2) ^ b_sw);
                    ldm4t(bh[q], rowb + coff);
                }
            }
            // ---- A frags per m-tile + single-pass mma ----
            #pragma unroll
            for (int mi = 0; mi < 3; mi++) {
                uint32_t aoff = (uint32_t)(warp_m * 48 + mi * 16 + (lane & 15)) * 80
                              + ks * 32 + (lane >> 4) * 16;
                unsigned ah[4];
                ldm4(ah, wbh + aoff);
                #pragma unroll
                for (int ni = 0; ni < 4; ni++)
                    mma16816(acc[mi][ni], ah, &bh[ni >> 1][(ni & 1) * 2]);
            }
        }
    }

    // ---- epilogue: stage kv in smem + fixed-order distance partials ----
    __syncthreads();   // mainloop smem reads done; dyn becomes [192][272B] staging

    float2 qv[4][3];
    #pragma unroll
    for (int ni = 0; ni < 4; ni++) {
        int hw = hw0 + warp_n * 32 + ni * 8 + 2 * tg;
        #pragma unroll
        for (int qq = 0; qq < 3; qq++)
            qv[ni][qq] = *(const float2*)&query[((size_t)b * DQ + qq) * HWN + hw];
    }

    #pragma unroll
    for (int mi = 0; mi < 3; mi++) {
        int m0 = warp_m * 48 + mi * 16 + g;
        int q0 = m0 % 3, q1 = (m0 + 8) % 3;
        float d0 = 0.f, d1 = 0.f;
        #pragma unroll
        for (int ni = 0; ni < 4; ni++) {
            int hwl = warp_n * 32 + ni * 8 + 2 * tg;
            float2 p0 = make_float2(acc[mi][ni][0], acc[mi][ni][1]);
            float2 p1 = make_float2(acc[mi][ni][2], acc[mi][ni][3]);
            *(unsigned*)(dyn + m0 * KV_PITCH + hwl * 2)       = cvt2(p0.x, p0.y);
            *(unsigned*)(dyn + (m0 + 8) * KV_PITCH + hwl * 2) = cvt2(p1.x, p1.y);
            float e0 = p0.x - qv[ni][q0].x, e1 = p0.y - qv[ni][q0].y;
            d0 += e0 * e0 + e1 * e1;
            float f0e = p1.x - qv[ni][q1].x, f1e = p1.y - qv[ni][q1].y;
            d1 += f0e * f0e + f1e * f1e;
        }
        d0 += __shfl_xor_sync(0xffffffffu, d0, 1);
        d0 += __shfl_xor_sync(0xffffffffu, d0, 2);
        d1 += __shfl_xor_sync(0xffffffffu, d1, 1);
        d1 += __shfl_xor_sync(0xffffffffu, d1, 2);
        if (tg == 0) {
            sdist[m0][warp_n]     = d0;
            sdist[m0 + 8][warp_n] = d1;
        }
    }
    __syncthreads();

    // coalesced copy: 192 rows x 256B; 512 threads -> 6 iterations
    #pragma unroll
    for (int t = 0; t < 6; t++) {
        int idx = tid + t * NTHREADS;
        int m = idx >> 4, c = idx & 15;
        uint4 v = *(uint4*)(dyn + m * KV_PITCH + c * 16);
        *(uint4*)&g_kv[((size_t)b * MM + m) * HWN + hw0 + c * 8] = v;
    }

    if (tid < KC) {
        float s = 0.f;
        #pragma unroll
        for (int qq = 0; qq < 3; qq++)
            #pragma unroll
            for (int wn = 0; wn < 4; wn++)
                s += sdist[tid * 3 + qq][wn];
        g_part[((size_t)b * NT + blockIdx.x) * KC + tid] = s;
    }
}

// ============================================================================
// Pass 2: gather + loss with inline per-batch argmin; last block finalizes
// the loss (fixed-order sum -> deterministic). Counter self-resets.
// ============================================================================
__global__ __launch_bounds__(256)
void gather_loss_kernel(const float* __restrict__ query,
                        float* __restrict__ out_sel,
                        float* __restrict__ out_codes,
                        float* __restrict__ out_loss) {
    const int blk = blockIdx.x;      // 0..95 (b*3+qq)
    const int ch  = blockIdx.y;      // 0..3
    const int b   = blk / DQ;
    const int qq  = blk % DQ;
    const int tid = threadIdx.x;

    __shared__ float sv[KC];
    __shared__ int   si[KC];
    if (tid < KC) {
        float s = 0.f;
        #pragma unroll 8
        for (int tt = 0; tt < NT; tt++)
            s += g_part[(b * NT + tt) * KC + tid];
        sv[tid] = s; si[tid] = tid;
    }
    __syncthreads();
    for (int off = 32; off > 0; off >>= 1) {
        if (tid < off) {
            float ov = sv[tid + off];
            int   oi = si[tid + off];
            if (ov < sv[tid] || (ov == sv[tid] && oi < si[tid])) { sv[tid] = ov; si[tid] = oi; }
        }
        __syncthreads();
    }
    const int code = si[0];
    if (tid == 0 && qq == 0 && ch == 0) out_codes[b] = (float)code;

    const int base = ch * 1024;
    const __half* src = &g_kv[((size_t)b * MM + code * DQ + qq) * HWN + base];
    const float*  qp  = &query[(size_t)(b * DQ + qq) * HWN + base];
    float*        dst = &out_sel[(size_t)(b * DQ + qq) * HWN + base];

    float s = 0.f;
    #pragma unroll
    for (int j = 0; j < 2; j++) {
        int i = (tid + j * 256) * 2;
        __half2 hv = *(const __half2*)(src + i);
        float2 v = __half22float2(hv);
        float2 qx = *(const float2*)(qp + i);
        *(float2*)(dst + i) = v;
        float d0 = v.x - qx.x, d1 = v.y - qx.y;
        s += d0 * d0 + d1 * d1;
    }
    __shared__ float red[256];
    red[tid] = s;
    __syncthreads();
    for (int off = 128; off > 0; off >>= 1) {
        if (tid < off) red[tid] += red[tid + off];
        __syncthreads();
    }

    __shared__ bool is_last;
    if (tid == 0) {
        g_loss[blk * 4 + ch] = red[0];
        __threadfence();
        unsigned t = atomicAdd(&g_cnt, 1u);
        is_last = (t == BB * DQ * 4 - 1);
    }
    __syncthreads();
    if (is_last) {
        if (tid < 128) {
            float t = g_loss[tid] + g_loss[tid + 128] + g_loss[tid + 256];
            red[tid] = t;
        }
        __syncthreads();
        for (int off = 64; off > 0; off >>= 1) {
            if (tid < off) red[tid] += red[tid + off];
            __syncthreads();
        }
        if (tid == 0) {
            *out_loss = red[0] / (float)((size_t)BB * DQ * HWN);
            g_cnt = 0;       // reset for next graph replay
        }
    }
}

// ============================================================================
extern "C" void kernel_launch(void* const* d_in, const int* in_sizes, int n_in,
                              void* d_out, int out_size) {
    const float* feat  = (const float*)d_in[0];
    const float* query = (const float*)d_in[1];
    const float* Wm    = (const float*)d_in[2];
    float* out = (float*)d_out;

    cudaFuncSetAttribute((const void*)kv_mma_kernel,
                         cudaFuncAttributeMaxDynamicSharedMemorySize, SMEM_TOT);

    wsplit_kernel<<<192, 256>>>(Wm);
    dim3 g1(NT, BB);
    kv_mma_kernel<<<g1, NTHREADS, SMEM_TOT>>>(feat, query);
    dim3 g3(BB * DQ, 4);
    gather_loss_kernel<<<g3, 256>>>(query, out,
                                    out + (size_t)BB * DQ * HWN,
                                    out + (size_t)BB * DQ * HWN + BB);
}

// round 15
// speedup vs baseline: 1.3885x; 1.3885x over previous
#include <cuda_runtime.h>
#include <cuda_fp16.h>
#include <cstdint>

#define BB   32
#define DIM  512
#define HWN  4096
#define KC   64
#define DQ   3
#define MM   192
#define NTILE 128           // hw per CTA
#define NT   32             // 4096/128
#define KSTAGE 32
#define NSTAGE 16           // 512/32

// dynamic smem layout (mainloop)
#define W_BUF_B   15360     // per buffer: hi only (192*80)
#define OFF_W     0
#define OFF_BH    30720     // fp16 feat [k32][n128] swizzled, 2 x 8192
// epilogue staging reuses dyn as [192][272B]: 52224 B
#define KV_PITCH  272
#define SMEM_TOT  52224

// ---------------- scratch ----------------
__device__ __half   g_kv[(size_t)BB * MM * HWN];     // [b][m][hw]  (fp16)
__device__ float    g_part[BB * NT * KC];
__device__ float    g_loss[BB * DQ * 4];
__device__ unsigned g_Whi[MM * DIM / 2];             // f16x2, [m][kpair]
__device__ unsigned g_cnt;                           // completion counter (self-resetting)

// ---------------- helpers ----------------
__device__ __forceinline__ uint32_t smem_u32(const void* p) {
    uint32_t a;
    asm("{ .reg .u64 t; cvta.to.shared.u64 t, %1; cvt.u32.u64 %0, t; }" : "=r"(a) : "l"(p));
    return a;
}
__device__ __forceinline__ void cp16(uint32_t smem, const void* gmem) {
    unsigned long long ga = (unsigned long long)__cvta_generic_to_global(gmem);
    asm volatile("cp.async.cg.shared.global [%0], [%1], 16;" :: "r"(smem), "l"(ga));
}
__device__ __forceinline__ void cp_commit() { asm volatile("cp.async.commit_group;"); }
__device__ __forceinline__ void cp_wait0() { asm volatile("cp.async.wait_group 0;" ::: "memory"); }

__device__ __forceinline__ void ldm4(unsigned* r, uint32_t a) {
    asm volatile("ldmatrix.sync.aligned.m8n8.x4.shared.b16 {%0,%1,%2,%3}, [%4];"
                 : "=r"(r[0]), "=r"(r[1]), "=r"(r[2]), "=r"(r[3]) : "r"(a));
}
__device__ __forceinline__ void ldm4t(unsigned* r, uint32_t a) {
    asm volatile("ldmatrix.sync.aligned.m8n8.x4.trans.shared.b16 {%0,%1,%2,%3}, [%4];"
                 : "=r"(r[0]), "=r"(r[1]), "=r"(r[2]), "=r"(r[3]) : "r"(a));
}
__device__ __forceinline__ void mma16816(float* c, const unsigned* a, const unsigned* b) {
    asm volatile("mma.sync.aligned.m16n8k16.row.col.f32.f16.f16.f32 "
                 "{%0,%1,%2,%3}, {%4,%5,%6,%7}, {%8,%9}, {%0,%1,%2,%3};"
                 : "+f"(c[0]), "+f"(c[1]), "+f"(c[2]), "+f"(c[3])
                 : "r"(a[0]), "r"(a[1]), "r"(a[2]), "r"(a[3]), "r"(b[0]), "r"(b[1]));
}
// pack fp16x2: {lo half = x0, hi half = x1}
__device__ __forceinline__ unsigned cvt2(float x0, float x1) {
    unsigned r;
    asm("cvt.rn.f16x2.f32 %0, %1, %2;" : "=r"(r) : "f"(x1), "f"(x0));
    return r;
}

// ============================================================================
// Pass 0: W fp32 -> fp16 packed k-pairs
// ============================================================================
__global__ void wsplit_kernel(const float* __restrict__ W) {
    int i = blockIdx.x * 256 + threadIdx.x;
    if (i >= MM * DIM / 2) return;
    g_Whi[i] = cvt2(W[2 * i], W[2 * i + 1]);
}

// ============================================================================
// Pass 1: C[m,hw] = W @ feat per batch via single-pass fp16 mma.sync.
// 256 threads, 8 warps = 4m x 2n (warp tile m48 x n64). Feat: direct
// LDG -> cvt -> STS, double-buffered fp16 B + W, one sync per stage.
// Epilogue: stage kv in smem (pitch 272, conflict-free) -> coalesced STG.128.
// ============================================================================
__global__ __launch_bounds__(256)
void kv_mma_kernel(const float* __restrict__ feat,
                   const float* __restrict__ query) {
    extern __shared__ __align__(16) unsigned char dyn[];
    __shared__ float sdist[MM][2];

    const int tid  = threadIdx.x;
    const int b    = blockIdx.y;
    const int hw0  = blockIdx.x * NTILE;
    const int lane = tid & 31, wid = tid >> 5;
    const int warp_m = wid >> 1;          // 0..3 -> m offset *48
    const int warp_n = wid & 1;           // 0..1 -> hw offset *64
    const int g  = lane >> 2, tg = lane & 3;

    const uint32_t sbase = smem_u32(dyn);

    // feat conversion addressing: thread covers k=ck, n=[cn, cn+16)
    const int ck = tid >> 3;
    const int cn = (tid & 7) * 16;
    const uint32_t sts0 = (uint32_t)(ck * 256 + (((cn * 2)     ) ^ ((ck & 7) << 4)));
    const uint32_t sts1 = (uint32_t)(ck * 256 + (((cn * 2) + 16) ^ ((ck & 7) << 4)));

    auto issueW = [&](int s, int buf) {
        const uint32_t wb = sbase + OFF_W + (uint32_t)buf * W_BUF_B;
        #pragma unroll
        for (int j = 0; j < 3; j++) {                // W hi: 192 rows x 4 chunks
            int i = tid + j * 256;
            int m = i >> 2, c = i & 3;
            cp16(wb + m * 80 + c * 16, g_Whi + m * 256 + s * 16 + c * 4);
        }
    };

    float acc[3][8][4];
    #pragma unroll
    for (int mi = 0; mi < 3; mi++)
        #pragma unroll
        for (int ni = 0; ni < 8; ni++)
            #pragma unroll
            for (int r = 0; r < 4; r++) acc[mi][ni][r] = 0.f;

    // B ldmatrix lane addressing
    const int b_r      = lane & 7;
    const int b_khalf  = (lane >> 3) & 1;
    const int b_nhalf  = (lane >> 4) & 1;
    const uint32_t b_sw = (uint32_t)(b_r << 4);
    const uint32_t b_n0 = (uint32_t)(warp_n * 64 + b_nhalf * 8);

    // prefetch feat stage 0
    float4 f0, f1, f2, f3;
    {
        const float* fp = feat + ((size_t)(b * DIM + ck)) * HWN + hw0 + cn;
        f0 = *(const float4*)(fp);
        f1 = *(const float4*)(fp + 4);
        f2 = *(const float4*)(fp + 8);
        f3 = *(const float4*)(fp + 12);
    }
    issueW(0, 0); cp_commit();

    for (int s = 0; s < NSTAGE; s++) {
        const int buf = s & 1;
        const uint32_t bhb = sbase + OFF_BH + (uint32_t)buf * 8192;

        // ---- convert this stage's feat regs -> fp16 smem ----
        {
            unsigned h0 = cvt2(f0.x, f0.y), h1 = cvt2(f0.z, f0.w);
            unsigned h2 = cvt2(f1.x, f1.y), h3 = cvt2(f1.z, f1.w);
            unsigned h4 = cvt2(f2.x, f2.y), h5 = cvt2(f2.z, f2.w);
            unsigned h6 = cvt2(f3.x, f3.y), h7 = cvt2(f3.z, f3.w);
            *(uint4*)(dyn + OFF_BH + buf * 8192 + sts0) = make_uint4(h0, h1, h2, h3);
            *(uint4*)(dyn + OFF_BH + buf * 8192 + sts1) = make_uint4(h4, h5, h6, h7);
        }
        // ---- prefetch feat for next stage ----
        if (s + 1 < NSTAGE) {
            const float* fp = feat + ((size_t)(b * DIM + (s + 1) * KSTAGE + ck)) * HWN + hw0 + cn;
            f0 = *(const float4*)(fp);
            f1 = *(const float4*)(fp + 4);
            f2 = *(const float4*)(fp + 8);
            f3 = *(const float4*)(fp + 12);
        }
        cp_wait0();          // W for stage s landed
        __syncthreads();     // the only barrier per stage
        if (s + 1 < NSTAGE) { issueW(s + 1, buf ^ 1); cp_commit(); }

        const uint32_t wbh = sbase + OFF_W + (uint32_t)buf * W_BUF_B;

        #pragma unroll
        for (int ks = 0; ks < 2; ks++) {
            // ---- B fragments via ldmatrix.trans: 4 quarters of n64 ----
            unsigned bh[4][4];
            {
                uint32_t k = (uint32_t)(ks * 16 + b_khalf * 8 + b_r);
                uint32_t rowb = bhb + k * 256;
                #pragma unroll
                for (int q = 0; q < 4; q++) {
                    uint32_t coff = (((b_n0 + q * 16) * 2) ^ b_sw);
                    ldm4t(bh[q], rowb + coff);
                }
            }
            // ---- A frags per m-tile + single-pass mma ----
            #pragma unroll
            for (int mi = 0; mi < 3; mi++) {
                uint32_t aoff = (uint32_t)(warp_m * 48 + mi * 16 + (lane & 15)) * 80
                              + ks * 32 + (lane >> 4) * 16;
                unsigned ah[4];
                ldm4(ah, wbh + aoff);
                #pragma unroll
                for (int ni = 0; ni < 8; ni++)
                    mma16816(acc[mi][ni], ah, &bh[ni >> 1][(ni & 1) * 2]);
            }
        }
    }

    // ---- epilogue: stage kv in smem + fixed-order distance partials ----
    __syncthreads();   // mainloop smem reads done; dyn becomes [192][272B] staging

    float2 qv[8][3];
    #pragma unroll
    for (int ni = 0; ni < 8; ni++) {
        int hw = hw0 + warp_n * 64 + ni * 8 + 2 * tg;
        #pragma unroll
        for (int qq = 0; qq < 3; qq++)
            qv[ni][qq] = *(const float2*)&query[((size_t)b * DQ + qq) * HWN + hw];
    }

    #pragma unroll
    for (int mi = 0; mi < 3; mi++) {
        int m0 = warp_m * 48 + mi * 16 + g;
        int q0 = m0 % 3, q1 = (m0 + 8) % 3;
        float d0 = 0.f, d1 = 0.f;
        #pragma unroll
        for (int ni = 0; ni < 8; ni++) {
            int hwl = warp_n * 64 + ni * 8 + 2 * tg;
            float2 p0 = make_float2(acc[mi][ni][0], acc[mi][ni][1]);
            float2 p1 = make_float2(acc[mi][ni][2], acc[mi][ni][3]);
            *(unsigned*)(dyn + m0 * KV_PITCH + hwl * 2)       = cvt2(p0.x, p0.y);
            *(unsigned*)(dyn + (m0 + 8) * KV_PITCH + hwl * 2) = cvt2(p1.x, p1.y);
            float e0 = p0.x - qv[ni][q0].x, e1 = p0.y - qv[ni][q0].y;
            d0 += e0 * e0 + e1 * e1;
            float f0e = p1.x - qv[ni][q1].x, f1e = p1.y - qv[ni][q1].y;
            d1 += f0e * f0e + f1e * f1e;
        }
        d0 += __shfl_xor_sync(0xffffffffu, d0, 1);
        d0 += __shfl_xor_sync(0xffffffffu, d0, 2);
        d1 += __shfl_xor_sync(0xffffffffu, d1, 1);
        d1 += __shfl_xor_sync(0xffffffffu, d1, 2);
        if (tg == 0) {
            sdist[m0][warp_n]     = d0;
            sdist[m0 + 8][warp_n] = d1;
        }
    }
    __syncthreads();

    // coalesced copy: 192 rows x 256B; each warp writes 2 full rows per step
    #pragma unroll
    for (int t = 0; t < 12; t++) {
        int idx = tid + t * 256;
        int m = idx >> 4, c = idx & 15;
        uint4 v = *(uint4*)(dyn + m * KV_PITCH + c * 16);
        *(uint4*)&g_kv[((size_t)b * MM + m) * HWN + hw0 + c * 8] = v;
    }

    if (tid < KC) {
        float s = 0.f;
        #pragma unroll
        for (int qq = 0; qq < 3; qq++)
            s += sdist[tid * 3 + qq][0] + sdist[tid * 3 + qq][1];
        g_part[((size_t)b * NT + blockIdx.x) * KC + tid] = s;
    }
}

// ============================================================================
// Pass 2: gather + loss with inline per-batch argmin; last block finalizes
// the loss (fixed-order sum -> deterministic). Counter self-resets.
// ============================================================================
__global__ __launch_bounds__(256)
void gather_loss_kernel(const float* __restrict__ query,
                        float* __restrict__ out_sel,
                        float* __restrict__ out_codes,
                        float* __restrict__ out_loss) {
    const int blk = blockIdx.x;      // 0..95 (b*3+qq)
    const int ch  = blockIdx.y;      // 0..3
    const int b   = blk / DQ;
    const int qq  = blk % DQ;
    const int tid = threadIdx.x;

    __shared__ float sv[KC];
    __shared__ int   si[KC];
    if (tid < KC) {
        float s = 0.f;
        #pragma unroll 8
        for (int tt = 0; tt < NT; tt++)
            s += g_part[(b * NT + tt) * KC + tid];
        sv[tid] = s; si[tid] = tid;
    }
    __syncthreads();
    for (int off = 32; off > 0; off >>= 1) {
        if (tid < off) {
            float ov = sv[tid + off];
            int   oi = si[tid + off];
            if (ov < sv[tid] || (ov == sv[tid] && oi < si[tid])) { sv[tid] = ov; si[tid] = oi; }
        }
        __syncthreads();
    }
    const int code = si[0];
    if (tid == 0 && qq == 0 && ch == 0) out_codes[b] = (float)code;

    const int base = ch * 1024;
    const __half* src = &g_kv[((size_t)b * MM + code * DQ + qq) * HWN + base];
    const float*  qp  = &query[(size_t)(b * DQ + qq) * HWN + base];
    float*        dst = &out_sel[(size_t)(b * DQ + qq) * HWN + base];

    float s = 0.f;
    #pragma unroll
    for (int j = 0; j < 2; j++) {
        int i = (tid + j * 256) * 2;
        __half2 hv = *(const __half2*)(src + i);
        float2 v = __half22float2(hv);
        float2 qx = *(const float2*)(qp + i);
        *(float2*)(dst + i) = v;
        float d0 = v.x - qx.x, d1 = v.y - qx.y;
        s += d0 * d0 + d1 * d1;
    }
    __shared__ float red[256];
    red[tid] = s;
    __syncthreads();
    for (int off = 128; off > 0; off >>= 1) {
        if (tid < off) red[tid] += red[tid + off];
        __syncthreads();
    }

    __shared__ bool is_last;
    if (tid == 0) {
        g_loss[blk * 4 + ch] = red[0];
        __threadfence();
        unsigned t = atomicAdd(&g_cnt, 1u);
        is_last = (t == BB * DQ * 4 - 1);
    }
    __syncthreads();
    if (is_last) {
        if (tid < 128) {
            float t = g_loss[tid] + g_loss[tid + 128] + g_loss[tid + 256];
            red[tid] = t;
        }
        __syncthreads();
        for (int off = 64; off > 0; off >>= 1) {
            if (tid < off) red[tid] += red[tid + off];
            __syncthreads();
        }
        if (tid == 0) {
            *out_loss = red[0] / (float)((size_t)BB * DQ * HWN);
            g_cnt = 0;       // reset for next graph replay
        }
    }
}

// ============================================================================
extern "C" void kernel_launch(void* const* d_in, const int* in_sizes, int n_in,
                              void* d_out, int out_size) {
    const float* feat  = (const float*)d_in[0];
    const float* query = (const float*)d_in[1];
    const float* Wm    = (const float*)d_in[2];
    float* out = (float*)d_out;

    cudaFuncSetAttribute((const void*)kv_mma_kernel,
                         cudaFuncAttributeMaxDynamicSharedMemorySize, SMEM_TOT);

    wsplit_kernel<<<192, 256>>>(Wm);
    dim3 g1(NT, BB);
    kv_mma_kernel<<<g1, 256, SMEM_TOT>>>(feat, query);
    dim3 g3(BB * DQ, 4);
    gather_loss_kernel<<<g3, 256>>>(query, out,
                                    out + (size_t)BB * DQ * HWN,
                                    out + (size_t)BB * DQ * HWN + BB);
}